// round 10
// baseline (speedup 1.0000x reference)
#include <cuda_runtime.h>
#include <cuda_fp16.h>

#define NN 100000
#define NE 3200000
#define NG 1024
#define HD 32
#define CAP 128
#define BN_EPS 1e-5f
#define FULL 0xffffffffu

// ---------------- scratch (no allocations allowed) ----------------
__device__ __half g_hsA[NN * HD];
__device__ __half g_hsB[NN * HD];
__device__ int    g_srcs[NN * CAP];   // bucket CSR, 128 slots per node
__device__ int    g_deg[NN];
__device__ float  g_dinv[NN];
__device__ float  g_xs[NN];           // x * dinv
__device__ float  g_cnt[NG];

// ---------------- helpers ----------------
__device__ __forceinline__ unsigned pack_h2(float a, float b) {
    __half2 h = __float22half2_rn(make_float2(a, b));
    return *(unsigned*)&h;
}

// ---------------- init ----------------
__global__ void k_init(float* out) {
    int i = blockIdx.x * blockDim.x + threadIdx.x;
    if (i < NN) g_deg[i] = 0;
    if (i < NG) g_cnt[i] = 0.0f;
    if (i < NG * HD) out[i] = 0.0f;
}

// ---------------- single-pass bucket-CSR fill (8 edges/thread) ----------------
__global__ void k_fill(const int* __restrict__ ei) {
    int t = blockIdx.x * blockDim.x + threadIdx.x;
    int e0 = t * 8;
    if (e0 >= NE) return;
    int4 s4a = *(const int4*)(ei + e0);
    int4 s4b = *(const int4*)(ei + e0 + 4);
    int4 d4a = *(const int4*)(ei + NE + e0);
    int4 d4b = *(const int4*)(ei + NE + e0 + 4);
    int srcs[8] = {s4a.x, s4a.y, s4a.z, s4a.w, s4b.x, s4b.y, s4b.z, s4b.w};
    int dsts[8] = {d4a.x, d4a.y, d4a.z, d4a.w, d4b.x, d4b.y, d4b.z, d4b.w};
#pragma unroll
    for (int k = 0; k < 8; k++) {
        int pos = atomicAdd(&g_deg[dsts[k]], 1);
        if (pos < CAP) g_srcs[dsts[k] * CAP + pos] = srcs[k];
    }
}

// ---------------- prep: dinv, xs, graph-size histogram ----------------
__global__ void k_prep(const float* __restrict__ x, const int* __restrict__ batch) {
    int i = blockIdx.x * blockDim.x + threadIdx.x;
    if (i >= NN) return;
    float dinv = rsqrtf((float)(g_deg[i] + 1));   // +1 self loop
    g_dinv[i] = dinv;
    g_xs[i]   = x[i] * dinv;
    atomicAdd(&g_cnt[batch[i]], 1.0f);
}

// ---------------- layer 1: 4 nodes/warp rank-1 gather + quad epilogue -> hsB ----
// quarter q = lane>>3 (node select), sub = lane&7; lane handles features 4*sub..+3.
__global__ __launch_bounds__(256)
void k_layer1(const float* __restrict__ W1, const float* __restrict__ b1,
              const float* __restrict__ bg, const float* __restrict__ bb,
              const float* __restrict__ bm, const float* __restrict__ bv,
              const float* __restrict__ W2) {
    __shared__ float sW[HD * HD];
    int tid = threadIdx.x;
    for (int i = tid; i < HD * HD; i += 256) sW[i] = W2[i];
    __syncthreads();
    int warp = tid >> 5, lane = tid & 31;
    int q = lane >> 3, sub = lane & 7;
    int node = blockIdx.x * 32 + warp * 4 + q;   // 3125 blocks exact
    int f0 = sub * 4;

    // chunked scalar gather: int4 srcs load -> 4 independent xs loads (MLP 4)
    float a = 0.0f;
    int beg = node * CAP;
    int dg = g_deg[node]; if (dg > CAP) dg = CAP;
    for (int jc = 0; jc < dg; jc += 32) {
        int4 sv = *(const int4*)&g_srcs[beg + jc + sub * 4];
        int jb = jc + sub * 4;
        float t0 = (jb + 0 < dg) ? g_xs[sv.x] : 0.0f;
        float t1 = (jb + 1 < dg) ? g_xs[sv.y] : 0.0f;
        float t2 = (jb + 2 < dg) ? g_xs[sv.z] : 0.0f;
        float t3 = (jb + 3 < dg) ? g_xs[sv.w] : 0.0f;
        a += (t0 + t1) + (t2 + t3);
    }
#pragma unroll
    for (int o = 4; o; o >>= 1) a += __shfl_xor_sync(FULL, a, o);  // reduce in group
    a += g_xs[node];                                 // self loop

    float dinv = g_dinv[node];
    float s = dinv * a;

    // 4 features/lane through linear1 + BN + ReLU
    float4 w1 = *(const float4*)&W1[f0];
    float4 bb1 = *(const float4*)&b1[f0];
    float4 vg = *(const float4*)&bg[f0];
    float4 vb = *(const float4*)&bb[f0];
    float4 vm = *(const float4*)&bm[f0];
    float4 vv = *(const float4*)&bv[f0];
    float y[4];
    {
        float A0 = vg.x * rsqrtf(vv.x + BN_EPS);
        float A1 = vg.y * rsqrtf(vv.y + BN_EPS);
        float A2 = vg.z * rsqrtf(vv.z + BN_EPS);
        float A3 = vg.w * rsqrtf(vv.w + BN_EPS);
        y[0] = fmaxf(fmaf(fmaf(s, w1.x, bb1.x), A0, fmaf(-vm.x, A0, vb.x)), 0.0f);
        y[1] = fmaxf(fmaf(fmaf(s, w1.y, bb1.y), A1, fmaf(-vm.y, A1, vb.y)), 0.0f);
        y[2] = fmaxf(fmaf(fmaf(s, w1.z, bb1.z), A2, fmaf(-vm.z, A2, vb.z)), 0.0f);
        y[3] = fmaxf(fmaf(fmaf(s, w1.w, bb1.w), A3, fmaf(-vm.w, A3, vb.w)), 0.0f);
    }

    // quad matvec epilogue: compile-time component & lane selects
    float o0 = 0.0f, o1 = 0.0f, o2 = 0.0f, o3 = 0.0f;
    int gbase = lane & 24;   // q*8
#pragma unroll
    for (int k = 0; k < 32; k++) {
        float yk = __shfl_sync(FULL, y[k & 3], gbase + (k >> 2));
        float4 w = *(const float4*)&sW[k * HD + f0];
        o0 = fmaf(yk, w.x, o0);
        o1 = fmaf(yk, w.y, o1);
        o2 = fmaf(yk, w.z, o2);
        o3 = fmaf(yk, w.w, o3);
    }
    uint2 pk = make_uint2(pack_h2(o0 * dinv, o1 * dinv), pack_h2(o2 * dinv, o3 * dinv));
    ((uint2*)g_hsB)[node * 8 + sub] = pk;
}

// ---------------- quad gather: 4 nodes/warp, chunked int4 index loads ----------
// returns float4 accumulation of features f0..f0+3 for this lane's node.
__device__ __forceinline__ float4 gather_quad(const uint2* __restrict__ rowp,
                                              int node, int sub, int lane) {
    uint2 selfv = rowp[node * 8 + sub];
    float2 alo = __half22float2(*(__half2*)&selfv.x);
    float2 ahi = __half22float2(*(__half2*)&selfv.y);
    int dg = g_deg[node]; if (dg > CAP) dg = CAP;
    int m1 = max(dg, __shfl_xor_sync(FULL, dg, 8));
    int dgmax = max(m1, __shfl_xor_sync(FULL, m1, 16));
    int beg = node * CAP;
    int gbase = lane & 24;
    for (int jc = 0; jc < dgmax; jc += 32) {
        int4 sv = *(const int4*)&g_srcs[beg + jc + sub * 4];  // in-bounds (CAP=128)
        int v[4] = {sv.x, sv.y, sv.z, sv.w};
#pragma unroll
        for (int k = 0; k < 32; k++) {
            int s = __shfl_sync(FULL, v[k & 3], gbase + (k >> 2));
            if (jc + k < dg) {
                uint2 r = rowp[s * 8 + sub];
                float2 lo = __half22float2(*(__half2*)&r.x);
                float2 hi = __half22float2(*(__half2*)&r.y);
                alo.x += lo.x; alo.y += lo.y; ahi.x += hi.x; ahi.y += hi.y;
            }
        }
    }
    return make_float4(alo.x, alo.y, ahi.x, ahi.y);
}

// ---------------- layer 2: gather hsB + BN + ReLU + W3 -> hsA ----------------
__global__ __launch_bounds__(256)
void k_mid(const float* __restrict__ b2,
           const float* __restrict__ bg, const float* __restrict__ bb,
           const float* __restrict__ bm, const float* __restrict__ bv,
           const float* __restrict__ W3) {
    __shared__ float sW[HD * HD];
    int tid = threadIdx.x;
    for (int i = tid; i < HD * HD; i += 256) sW[i] = W3[i];
    __syncthreads();
    int warp = tid >> 5, lane = tid & 31;
    int q = lane >> 3, sub = lane & 7;
    int node = blockIdx.x * 32 + warp * 4 + q;   // 3125 blocks exact
    int f0 = sub * 4;

    float4 acc = gather_quad((const uint2*)g_hsB, node, sub, lane);
    float dinv = g_dinv[node];

    float4 bv2 = *(const float4*)&b2[f0];
    float4 vg = *(const float4*)&bg[f0];
    float4 vb = *(const float4*)&bb[f0];
    float4 vm = *(const float4*)&bm[f0];
    float4 vv = *(const float4*)&bv[f0];
    float y[4];
    {
        float A0 = vg.x * rsqrtf(vv.x + BN_EPS);
        float A1 = vg.y * rsqrtf(vv.y + BN_EPS);
        float A2 = vg.z * rsqrtf(vv.z + BN_EPS);
        float A3 = vg.w * rsqrtf(vv.w + BN_EPS);
        y[0] = fmaxf(fmaf(fmaf(dinv, acc.x, bv2.x), A0, fmaf(-vm.x, A0, vb.x)), 0.0f);
        y[1] = fmaxf(fmaf(fmaf(dinv, acc.y, bv2.y), A1, fmaf(-vm.y, A1, vb.y)), 0.0f);
        y[2] = fmaxf(fmaf(fmaf(dinv, acc.z, bv2.z), A2, fmaf(-vm.z, A2, vb.z)), 0.0f);
        y[3] = fmaxf(fmaf(fmaf(dinv, acc.w, bv2.w), A3, fmaf(-vm.w, A3, vb.w)), 0.0f);
    }

    float o0 = 0.0f, o1 = 0.0f, o2 = 0.0f, o3 = 0.0f;
    int gbase = lane & 24;
#pragma unroll
    for (int k = 0; k < 32; k++) {
        float yk = __shfl_sync(FULL, y[k & 3], gbase + (k >> 2));
        float4 w = *(const float4*)&sW[k * HD + f0];
        o0 = fmaf(yk, w.x, o0);
        o1 = fmaf(yk, w.y, o1);
        o2 = fmaf(yk, w.z, o2);
        o3 = fmaf(yk, w.w, o3);
    }
    uint2 pk = make_uint2(pack_h2(o0 * dinv, o1 * dinv), pack_h2(o2 * dinv, o3 * dinv));
    ((uint2*)g_hsA)[node * 8 + sub] = pk;
}

// ---------------- final: gather hsA + bias, block-aggregated pool ----------------
__global__ __launch_bounds__(256)
void k_final(const float* __restrict__ b3,
             const int* __restrict__ batch, float* __restrict__ out) {
    __shared__ float sacc[32][HD];
    __shared__ int   sg[32];
    int tid = threadIdx.x;
    int warp = tid >> 5, lane = tid & 31;
    int q = lane >> 3, sub = lane & 7;
    int node = blockIdx.x * 32 + warp * 4 + q;
    int f0 = sub * 4;
    int nl = warp * 4 + q;

    float4 acc = gather_quad((const uint2*)g_hsA, node, sub, lane);
    float dinv = g_dinv[node];
    float4 b = *(const float4*)&b3[f0];
    float4 o;
    o.x = fmaf(dinv, acc.x, b.x);
    o.y = fmaf(dinv, acc.y, b.y);
    o.z = fmaf(dinv, acc.z, b.z);
    o.w = fmaf(dinv, acc.w, b.w);
    if (sub == 0) sg[nl] = batch[node];
    *(float4*)&sacc[nl][f0] = o;
    __syncthreads();

    if (warp == 0) {
        int g0 = sg[0];
        bool uni = true;
#pragma unroll
        for (int w = 1; w < 32; w++) uni &= (sg[w] == g0);
        if (uni) {
            float s = 0.0f;
#pragma unroll
            for (int w = 0; w < 32; w++) s += sacc[w][lane];
            atomicAdd(&out[g0 * HD + lane], s);
        } else {
#pragma unroll
            for (int w = 0; w < 32; w++)
                atomicAdd(&out[sg[w] * HD + lane], sacc[w][lane]);
        }
    }
}

// ---------------- divide by counts ----------------
__global__ void k_div(float* out) {
    int i = blockIdx.x * blockDim.x + threadIdx.x;
    if (i >= NG * HD) return;
    float c = g_cnt[i >> 5];
    out[i] = out[i] / fmaxf(c, 1.0f);
}

extern "C" void kernel_launch(void* const* d_in, const int* in_sizes, int n_in,
                              void* d_out, int out_size) {
    const float* x     = (const float*)d_in[0];
    const int*   ei    = (const int*)d_in[1];
    const int*   batch = (const int*)d_in[2];
    const float* W1 = (const float*)d_in[3];
    const float* b1 = (const float*)d_in[4];
    const float* g1 = (const float*)d_in[5];
    const float* B1 = (const float*)d_in[6];
    const float* m1 = (const float*)d_in[7];
    const float* v1 = (const float*)d_in[8];
    const float* W2 = (const float*)d_in[9];
    const float* b2 = (const float*)d_in[10];
    const float* g2 = (const float*)d_in[11];
    const float* B2 = (const float*)d_in[12];
    const float* m2 = (const float*)d_in[13];
    const float* v2 = (const float*)d_in[14];
    const float* W3 = (const float*)d_in[15];
    const float* b3 = (const float*)d_in[16];
    float* out = (float*)d_out;

    const int T = 256;
    k_init<<<(NN + T - 1) / T, T>>>(out);
    k_fill<<<(NE / 8 + T - 1) / T, T>>>(ei);
    k_prep<<<(NN + T - 1) / T, T>>>(x, batch);

    k_layer1<<<NN / 32, T>>>(W1, b1, g1, B1, m1, v1, W2);
    k_mid<<<NN / 32, T>>>(b2, g2, B2, m2, v2, W3);
    k_final<<<NN / 32, T>>>(b3, batch, out);
    k_div<<<(NG * HD + T - 1) / T, T>>>(out);
}

// round 11
// speedup vs baseline: 1.0641x; 1.0641x over previous
#include <cuda_runtime.h>
#include <cuda_fp16.h>

#define NN 100000
#define NE 3200000
#define NG 1024
#define HD 32
#define CAP 128
#define BN_EPS 1e-5f
#define FULL 0xffffffffu

// ---------------- scratch (no allocations allowed) ----------------
__device__ __half  g_hsA[NN * HD];    // layer-2 output rows (fp16)
__device__ float2  g_sv[NN];          // (s_i, dinv_i) from layer 1
__device__ int     g_srcs[NN * CAP];  // bucket CSR, 128 slots per node
__device__ int     g_deg[NN];
__device__ float   g_dinv[NN];
__device__ float   g_xs[NN];          // x * dinv
__device__ float   g_cnt[NG];

// ---------------- helpers ----------------
__device__ __forceinline__ unsigned pack_h2(float a, float b) {
    __half2 h = __float22half2_rn(make_float2(a, b));
    return *(unsigned*)&h;
}

// ---------------- init ----------------
__global__ void k_init(float* out) {
    int i = blockIdx.x * blockDim.x + threadIdx.x;
    if (i < NN) g_deg[i] = 0;
    if (i < NG) g_cnt[i] = 0.0f;
    if (i < NG * HD) out[i] = 0.0f;
}

// ---------------- single-pass bucket-CSR fill (8 edges/thread) ----------------
__global__ void k_fill(const int* __restrict__ ei) {
    int t = blockIdx.x * blockDim.x + threadIdx.x;
    int e0 = t * 8;
    if (e0 >= NE) return;
    int4 s4a = *(const int4*)(ei + e0);
    int4 s4b = *(const int4*)(ei + e0 + 4);
    int4 d4a = *(const int4*)(ei + NE + e0);
    int4 d4b = *(const int4*)(ei + NE + e0 + 4);
    int srcs[8] = {s4a.x, s4a.y, s4a.z, s4a.w, s4b.x, s4b.y, s4b.z, s4b.w};
    int dsts[8] = {d4a.x, d4a.y, d4a.z, d4a.w, d4b.x, d4b.y, d4b.z, d4b.w};
#pragma unroll
    for (int k = 0; k < 8; k++) {
        int pos = atomicAdd(&g_deg[dsts[k]], 1);
        if (pos < CAP) g_srcs[dsts[k] * CAP + pos] = srcs[k];
    }
}

// ---------------- prep: dinv, xs, graph-size histogram ----------------
__global__ void k_prep(const float* __restrict__ x, const int* __restrict__ batch) {
    int i = blockIdx.x * blockDim.x + threadIdx.x;
    if (i >= NN) return;
    float dinv = rsqrtf((float)(g_deg[i] + 1));   // +1 self loop
    g_dinv[i] = dinv;
    g_xs[i]   = x[i] * dinv;
    atomicAdd(&g_cnt[batch[i]], 1.0f);
}

// ---------------- layer 1 (reduced): s_i = dinv_i*(sum xs_j + xs_i) -> g_sv ----
// 4 nodes/warp, 8 lanes/node; chunked int4 srcs -> 4 independent xs loads.
__global__ __launch_bounds__(256)
void k_layer1() {
    int tid = threadIdx.x;
    int warp = tid >> 5, lane = tid & 31;
    int q = lane >> 3, sub = lane & 7;
    int node = blockIdx.x * 32 + warp * 4 + q;   // 3125 blocks exact

    float a = 0.0f;
    int beg = node * CAP;
    int dg = g_deg[node]; if (dg > CAP) dg = CAP;
    for (int jc = 0; jc < dg; jc += 32) {
        int4 sv = *(const int4*)&g_srcs[beg + jc + sub * 4];
        int jb = jc + sub * 4;
        float t0 = (jb + 0 < dg) ? g_xs[sv.x] : 0.0f;
        float t1 = (jb + 1 < dg) ? g_xs[sv.y] : 0.0f;
        float t2 = (jb + 2 < dg) ? g_xs[sv.z] : 0.0f;
        float t3 = (jb + 3 < dg) ? g_xs[sv.w] : 0.0f;
        a += (t0 + t1) + (t2 + t3);
    }
#pragma unroll
    for (int o = 4; o; o >>= 1) a += __shfl_xor_sync(FULL, a, o);
    a += g_xs[node];                              // self loop

    if (sub == 0) {
        float dinv = g_dinv[node];
        g_sv[node] = make_float2(dinv * a, dinv);
    }
}

// ---------------- layer 2: scalar-broadcast gather + W2 + BN2 + relu + W3 -> hsA
// On-the-fly h1 features: y_jf = relu(P_f*s_j + Q_f); gather G = sum dinv_j*y_j.
__global__ __launch_bounds__(256)
void k_mid(const float* __restrict__ W1, const float* __restrict__ b1,
           const float* __restrict__ g1, const float* __restrict__ B1,
           const float* __restrict__ m1, const float* __restrict__ v1,
           const float* __restrict__ W2, const float* __restrict__ b2,
           const float* __restrict__ g2, const float* __restrict__ B2,
           const float* __restrict__ m2, const float* __restrict__ v2,
           const float* __restrict__ W3) {
    __shared__ float sW2[HD * HD];
    __shared__ float sW3[HD * HD];
    int tid = threadIdx.x;
    for (int i = tid; i < HD * HD; i += 256) { sW2[i] = W2[i]; sW3[i] = W3[i]; }
    __syncthreads();
    int warp = tid >> 5, lane = tid & 31;
    int q = lane >> 3, sub = lane & 7;
    int node = blockIdx.x * 32 + warp * 4 + q;   // 3125 blocks exact
    int f0 = sub * 4;
    int gbase = lane & 24;

    // per-lane affine constants for layer-1 features f0..f0+3
    float4 vw1 = *(const float4*)&W1[f0];
    float4 vb1 = *(const float4*)&b1[f0];
    float4 vg1 = *(const float4*)&g1[f0];
    float4 vB1 = *(const float4*)&B1[f0];
    float4 vm1 = *(const float4*)&m1[f0];
    float4 vv1 = *(const float4*)&v1[f0];
    float A0 = vg1.x * rsqrtf(vv1.x + BN_EPS);
    float A1 = vg1.y * rsqrtf(vv1.y + BN_EPS);
    float A2 = vg1.z * rsqrtf(vv1.z + BN_EPS);
    float A3 = vg1.w * rsqrtf(vv1.w + BN_EPS);
    float P0 = A0 * vw1.x, P1 = A1 * vw1.y, P2 = A2 * vw1.z, P3 = A3 * vw1.w;
    float Q0 = fmaf(A0, vb1.x, fmaf(-vm1.x, A0, vB1.x));
    float Q1 = fmaf(A1, vb1.y, fmaf(-vm1.y, A1, vB1.y));
    float Q2 = fmaf(A2, vb1.z, fmaf(-vm1.z, A2, vB1.z));
    float Q3 = fmaf(A3, vb1.w, fmaf(-vm1.w, A3, vB1.w));

    // self term
    float2 self = g_sv[node];
    float dinv = self.y;
    float G0 = dinv * fmaxf(fmaf(P0, self.x, Q0), 0.0f);
    float G1 = dinv * fmaxf(fmaf(P1, self.x, Q1), 0.0f);
    float G2 = dinv * fmaxf(fmaf(P2, self.x, Q2), 0.0f);
    float G3 = dinv * fmaxf(fmaf(P3, self.x, Q3), 0.0f);

    // neighbor gather (R8-style 8-groups, idx sentinel)
    int dg = g_deg[node]; if (dg > CAP) dg = CAP;
    int mm1 = max(dg, __shfl_xor_sync(FULL, dg, 8));
    int dgmax = max(mm1, __shfl_xor_sync(FULL, mm1, 16));
    int beg = node * CAP;
    for (int j = 0; j < dgmax; j += 8) {
        int idx = (j + sub < dg) ? g_srcs[beg + j + sub] : -1;
        int m = dgmax - j; if (m > 8) m = 8;
        if (m == 8) {
#pragma unroll
            for (int k = 0; k < 8; k++) {
                int s = __shfl_sync(FULL, idx, gbase + k);
                if (s >= 0) {
                    float2 v = g_sv[s];
                    G0 = fmaf(v.y, fmaxf(fmaf(P0, v.x, Q0), 0.0f), G0);
                    G1 = fmaf(v.y, fmaxf(fmaf(P1, v.x, Q1), 0.0f), G1);
                    G2 = fmaf(v.y, fmaxf(fmaf(P2, v.x, Q2), 0.0f), G2);
                    G3 = fmaf(v.y, fmaxf(fmaf(P3, v.x, Q3), 0.0f), G3);
                }
            }
        } else {
            for (int k = 0; k < m; k++) {
                int s = __shfl_sync(FULL, idx, gbase + k);
                if (s >= 0) {
                    float2 v = g_sv[s];
                    G0 = fmaf(v.y, fmaxf(fmaf(P0, v.x, Q0), 0.0f), G0);
                    G1 = fmaf(v.y, fmaxf(fmaf(P1, v.x, Q1), 0.0f), G1);
                    G2 = fmaf(v.y, fmaxf(fmaf(P2, v.x, Q2), 0.0f), G2);
                    G3 = fmaf(v.y, fmaxf(fmaf(P3, v.x, Q3), 0.0f), G3);
                }
            }
        }
    }

    // Ghat = dinv_i * G; matvec W2 + bias b2
    float Gh[4] = {dinv * G0, dinv * G1, dinv * G2, dinv * G3};
    float4 vb2 = *(const float4*)&b2[f0];
    float t0 = vb2.x, t1 = vb2.y, t2 = vb2.z, t3 = vb2.w;
#pragma unroll
    for (int k = 0; k < 32; k++) {
        float gk = __shfl_sync(FULL, Gh[k & 3], gbase + (k >> 2));
        float4 w = *(const float4*)&sW2[k * HD + f0];
        t0 = fmaf(gk, w.x, t0);
        t1 = fmaf(gk, w.y, t1);
        t2 = fmaf(gk, w.z, t2);
        t3 = fmaf(gk, w.w, t3);
    }

    // BN2 + relu
    float4 vg2 = *(const float4*)&g2[f0];
    float4 vB2 = *(const float4*)&B2[f0];
    float4 vm2 = *(const float4*)&m2[f0];
    float4 vv2 = *(const float4*)&v2[f0];
    float y[4];
    {
        float C0 = vg2.x * rsqrtf(vv2.x + BN_EPS);
        float C1 = vg2.y * rsqrtf(vv2.y + BN_EPS);
        float C2 = vg2.z * rsqrtf(vv2.z + BN_EPS);
        float C3 = vg2.w * rsqrtf(vv2.w + BN_EPS);
        y[0] = fmaxf(fmaf(t0, C0, fmaf(-vm2.x, C0, vB2.x)), 0.0f);
        y[1] = fmaxf(fmaf(t1, C1, fmaf(-vm2.y, C1, vB2.y)), 0.0f);
        y[2] = fmaxf(fmaf(t2, C2, fmaf(-vm2.z, C2, vB2.z)), 0.0f);
        y[3] = fmaxf(fmaf(t3, C3, fmaf(-vm2.w, C3, vB2.w)), 0.0f);
    }

    // matvec W3; store dinv * o as fp16 row
    float o0 = 0.0f, o1 = 0.0f, o2 = 0.0f, o3 = 0.0f;
#pragma unroll
    for (int k = 0; k < 32; k++) {
        float yk = __shfl_sync(FULL, y[k & 3], gbase + (k >> 2));
        float4 w = *(const float4*)&sW3[k * HD + f0];
        o0 = fmaf(yk, w.x, o0);
        o1 = fmaf(yk, w.y, o1);
        o2 = fmaf(yk, w.z, o2);
        o3 = fmaf(yk, w.w, o3);
    }
    uint2 pk = make_uint2(pack_h2(o0 * dinv, o1 * dinv), pack_h2(o2 * dinv, o3 * dinv));
    ((uint2*)g_hsA)[node * 8 + sub] = pk;
}

// ---------------- quad row gather (R8 form): 4 nodes/warp, 8 lanes x 4 halves ---
__device__ __forceinline__ float4 gather_quad(const uint2* __restrict__ rowp,
                                              int node, int sub, int lane) {
    uint2 selfv = rowp[node * 8 + sub];
    float2 alo = __half22float2(*(__half2*)&selfv.x);
    float2 ahi = __half22float2(*(__half2*)&selfv.y);
    int dg = g_deg[node]; if (dg > CAP) dg = CAP;
    int m1 = max(dg, __shfl_xor_sync(FULL, dg, 8));
    int dgmax = max(m1, __shfl_xor_sync(FULL, m1, 16));
    int beg = node * CAP;
    int gbase = lane & 24;
    for (int j = 0; j < dgmax; j += 8) {
        int idx = (j + sub < dg) ? g_srcs[beg + j + sub] : -1;
        int m = dgmax - j; if (m > 8) m = 8;
        if (m == 8) {
#pragma unroll
            for (int k = 0; k < 8; k++) {
                int s = __shfl_sync(FULL, idx, gbase + k);
                if (s >= 0) {
                    uint2 v = rowp[s * 8 + sub];
                    float2 lo = __half22float2(*(__half2*)&v.x);
                    float2 hi = __half22float2(*(__half2*)&v.y);
                    alo.x += lo.x; alo.y += lo.y; ahi.x += hi.x; ahi.y += hi.y;
                }
            }
        } else {
            for (int k = 0; k < m; k++) {
                int s = __shfl_sync(FULL, idx, gbase + k);
                if (s >= 0) {
                    uint2 v = rowp[s * 8 + sub];
                    float2 lo = __half22float2(*(__half2*)&v.x);
                    float2 hi = __half22float2(*(__half2*)&v.y);
                    alo.x += lo.x; alo.y += lo.y; ahi.x += hi.x; ahi.y += hi.y;
                }
            }
        }
    }
    return make_float4(alo.x, alo.y, ahi.x, ahi.y);
}

// ---------------- final: gather hsA + bias, block-aggregated pool ----------------
__global__ __launch_bounds__(256)
void k_final(const float* __restrict__ b3,
             const int* __restrict__ batch, float* __restrict__ out) {
    __shared__ float sacc[32][HD];
    __shared__ int   sg[32];
    int tid = threadIdx.x;
    int warp = tid >> 5, lane = tid & 31;
    int q = lane >> 3, sub = lane & 7;
    int node = blockIdx.x * 32 + warp * 4 + q;
    int f0 = sub * 4;
    int nl = warp * 4 + q;

    float4 acc = gather_quad((const uint2*)g_hsA, node, sub, lane);
    float dinv = g_dinv[node];
    float4 b = *(const float4*)&b3[f0];
    float4 o;
    o.x = fmaf(dinv, acc.x, b.x);
    o.y = fmaf(dinv, acc.y, b.y);
    o.z = fmaf(dinv, acc.z, b.z);
    o.w = fmaf(dinv, acc.w, b.w);
    if (sub == 0) sg[nl] = batch[node];
    *(float4*)&sacc[nl][f0] = o;
    __syncthreads();

    if (warp == 0) {
        int g0 = sg[0];
        bool uni = true;
#pragma unroll
        for (int w = 1; w < 32; w++) uni &= (sg[w] == g0);
        if (uni) {
            float s = 0.0f;
#pragma unroll
            for (int w = 0; w < 32; w++) s += sacc[w][lane];
            atomicAdd(&out[g0 * HD + lane], s);
        } else {
#pragma unroll
            for (int w = 0; w < 32; w++)
                atomicAdd(&out[sg[w] * HD + lane], sacc[w][lane]);
        }
    }
}

// ---------------- divide by counts ----------------
__global__ void k_div(float* out) {
    int i = blockIdx.x * blockDim.x + threadIdx.x;
    if (i >= NG * HD) return;
    float c = g_cnt[i >> 5];
    out[i] = out[i] / fmaxf(c, 1.0f);
}

extern "C" void kernel_launch(void* const* d_in, const int* in_sizes, int n_in,
                              void* d_out, int out_size) {
    const float* x     = (const float*)d_in[0];
    const int*   ei    = (const int*)d_in[1];
    const int*   batch = (const int*)d_in[2];
    const float* W1 = (const float*)d_in[3];
    const float* b1 = (const float*)d_in[4];
    const float* g1 = (const float*)d_in[5];
    const float* B1 = (const float*)d_in[6];
    const float* m1 = (const float*)d_in[7];
    const float* v1 = (const float*)d_in[8];
    const float* W2 = (const float*)d_in[9];
    const float* b2 = (const float*)d_in[10];
    const float* g2 = (const float*)d_in[11];
    const float* B2 = (const float*)d_in[12];
    const float* m2 = (const float*)d_in[13];
    const float* v2 = (const float*)d_in[14];
    const float* W3 = (const float*)d_in[15];
    const float* b3 = (const float*)d_in[16];
    float* out = (float*)d_out;

    const int T = 256;
    k_init<<<(NN + T - 1) / T, T>>>(out);
    k_fill<<<(NE / 8 + T - 1) / T, T>>>(ei);
    k_prep<<<(NN + T - 1) / T, T>>>(x, batch);

    k_layer1<<<NN / 32, T>>>();
    k_mid<<<NN / 32, T>>>(W1, b1, g1, B1, m1, v1, W2, b2, g2, B2, m2, v2, W3);
    k_final<<<NN / 32, T>>>(b3, batch, out);
    k_div<<<(NG * HD + T - 1) / T, T>>>(out);
}

// round 16
// speedup vs baseline: 1.1539x; 1.0844x over previous
#include <cuda_runtime.h>
#include <cuda_fp16.h>

#define NN 100000
#define NE 3200000
#define NG 1024
#define HD 32
#define CAP 128
#define BN_EPS 1e-5f
#define FULL 0xffffffffu

// ---------------- scratch (no allocations allowed) ----------------
__device__ uint2   g_z[NN * 8];      // z = dinv*y2 rows, fp16 (64B/row)
__device__ float2  g_sv[NN];         // (s_i, dinv_i) from layer 1
__device__ int     g_srcs[NN * CAP]; // bucket CSR, 128 slots per node
__device__ int     g_deg[NN];
__device__ float   g_dinv[NN];
__device__ float   g_xs[NN];         // x * dinv
__device__ float   g_cnt[NG];
__device__ float   g_pool[NG * HD];  // pooled pre-W3 vectors

// ---------------- helpers ----------------
__device__ __forceinline__ unsigned pack_h2(float a, float b) {
    __half2 h = __float22half2_rn(make_float2(a, b));
    return *(unsigned*)&h;
}

// ---------------- init ----------------
__global__ void k_init() {
    int i = blockIdx.x * blockDim.x + threadIdx.x;
    if (i < NN) g_deg[i] = 0;
    if (i < NG) g_cnt[i] = 0.0f;
    if (i < NG * HD) g_pool[i] = 0.0f;
}

// ---------------- single-pass bucket-CSR fill (8 edges/thread) ----------------
__global__ void k_fill(const int* __restrict__ ei) {
    int t = blockIdx.x * blockDim.x + threadIdx.x;
    int e0 = t * 8;
    if (e0 >= NE) return;
    int4 s4a = *(const int4*)(ei + e0);
    int4 s4b = *(const int4*)(ei + e0 + 4);
    int4 d4a = *(const int4*)(ei + NE + e0);
    int4 d4b = *(const int4*)(ei + NE + e0 + 4);
    int srcs[8] = {s4a.x, s4a.y, s4a.z, s4a.w, s4b.x, s4b.y, s4b.z, s4b.w};
    int dsts[8] = {d4a.x, d4a.y, d4a.z, d4a.w, d4b.x, d4b.y, d4b.z, d4b.w};
#pragma unroll
    for (int k = 0; k < 8; k++) {
        int pos = atomicAdd(&g_deg[dsts[k]], 1);
        if (pos < CAP) g_srcs[dsts[k] * CAP + pos] = srcs[k];
    }
}

// ---------------- prep: dinv, xs, graph-size histogram ----------------
__global__ void k_prep(const float* __restrict__ x, const int* __restrict__ batch) {
    int i = blockIdx.x * blockDim.x + threadIdx.x;
    if (i >= NN) return;
    float dinv = rsqrtf((float)(g_deg[i] + 1));   // +1 self loop
    g_dinv[i] = dinv;
    g_xs[i]   = x[i] * dinv;
    atomicAdd(&g_cnt[batch[i]], 1.0f);
}

// ---------------- layer 1 (reduced): s_i = dinv_i*(sum xs_j + xs_i) -> g_sv ----
__global__ __launch_bounds__(256)
void k_layer1() {
    int tid = threadIdx.x;
    int warp = tid >> 5, lane = tid & 31;
    int q = lane >> 3, sub = lane & 7;
    int node = blockIdx.x * 32 + warp * 4 + q;   // 3125 blocks exact

    float a = 0.0f;
    int beg = node * CAP;
    int dg = g_deg[node]; if (dg > CAP) dg = CAP;
    for (int jc = 0; jc < dg; jc += 32) {
        int4 sv = *(const int4*)&g_srcs[beg + jc + sub * 4];
        int jb = jc + sub * 4;
        float t0 = (jb + 0 < dg) ? g_xs[sv.x] : 0.0f;
        float t1 = (jb + 1 < dg) ? g_xs[sv.y] : 0.0f;
        float t2 = (jb + 2 < dg) ? g_xs[sv.z] : 0.0f;
        float t3 = (jb + 3 < dg) ? g_xs[sv.w] : 0.0f;
        a += (t0 + t1) + (t2 + t3);
    }
#pragma unroll
    for (int o = 4; o; o >>= 1) a += __shfl_xor_sync(FULL, a, o);
    a += g_xs[node];                              // self loop

    if (sub == 0) {
        float dinv = g_dinv[node];
        g_sv[node] = make_float2(dinv * a, dinv);
    }
}

// ---------------- layer 2: scalar gather + W2 + BN2 + relu -> z (fp16) --------
__global__ __launch_bounds__(256)
void k_mid(const float* __restrict__ W1, const float* __restrict__ b1,
           const float* __restrict__ g1, const float* __restrict__ B1,
           const float* __restrict__ m1, const float* __restrict__ v1,
           const float* __restrict__ W2, const float* __restrict__ b2,
           const float* __restrict__ g2, const float* __restrict__ B2,
           const float* __restrict__ m2, const float* __restrict__ v2) {
    __shared__ float sW2[HD * HD];
    int tid = threadIdx.x;
    for (int i = tid; i < HD * HD; i += 256) sW2[i] = W2[i];
    __syncthreads();
    int warp = tid >> 5, lane = tid & 31;
    int q = lane >> 3, sub = lane & 7;
    int node = blockIdx.x * 32 + warp * 4 + q;   // 3125 blocks exact
    int f0 = sub * 4;
    int gbase = lane & 24;

    // per-lane affine constants for layer-1 features f0..f0+3
    float4 vw1 = *(const float4*)&W1[f0];
    float4 vb1 = *(const float4*)&b1[f0];
    float4 vg1 = *(const float4*)&g1[f0];
    float4 vB1 = *(const float4*)&B1[f0];
    float4 vm1 = *(const float4*)&m1[f0];
    float4 vv1 = *(const float4*)&v1[f0];
    float A0 = vg1.x * rsqrtf(vv1.x + BN_EPS);
    float A1 = vg1.y * rsqrtf(vv1.y + BN_EPS);
    float A2 = vg1.z * rsqrtf(vv1.z + BN_EPS);
    float A3 = vg1.w * rsqrtf(vv1.w + BN_EPS);
    float P0 = A0 * vw1.x, P1 = A1 * vw1.y, P2 = A2 * vw1.z, P3 = A3 * vw1.w;
    float Q0 = fmaf(A0, vb1.x, fmaf(-vm1.x, A0, vB1.x));
    float Q1 = fmaf(A1, vb1.y, fmaf(-vm1.y, A1, vB1.y));
    float Q2 = fmaf(A2, vb1.z, fmaf(-vm1.z, A2, vB1.z));
    float Q3 = fmaf(A3, vb1.w, fmaf(-vm1.w, A3, vB1.w));

    // self term
    float2 self = g_sv[node];
    float dinv = self.y;
    float G0 = dinv * fmaxf(fmaf(P0, self.x, Q0), 0.0f);
    float G1 = dinv * fmaxf(fmaf(P1, self.x, Q1), 0.0f);
    float G2 = dinv * fmaxf(fmaf(P2, self.x, Q2), 0.0f);
    float G3 = dinv * fmaxf(fmaf(P3, self.x, Q3), 0.0f);

    // neighbor gather (8-groups, idx sentinel)
    int dg = g_deg[node]; if (dg > CAP) dg = CAP;
    int mm1 = max(dg, __shfl_xor_sync(FULL, dg, 8));
    int dgmax = max(mm1, __shfl_xor_sync(FULL, mm1, 16));
    int beg = node * CAP;
    for (int j = 0; j < dgmax; j += 8) {
        int idx = (j + sub < dg) ? g_srcs[beg + j + sub] : -1;
        int m = dgmax - j; if (m > 8) m = 8;
        if (m == 8) {
#pragma unroll
            for (int k = 0; k < 8; k++) {
                int s = __shfl_sync(FULL, idx, gbase + k);
                if (s >= 0) {
                    float2 v = g_sv[s];
                    G0 = fmaf(v.y, fmaxf(fmaf(P0, v.x, Q0), 0.0f), G0);
                    G1 = fmaf(v.y, fmaxf(fmaf(P1, v.x, Q1), 0.0f), G1);
                    G2 = fmaf(v.y, fmaxf(fmaf(P2, v.x, Q2), 0.0f), G2);
                    G3 = fmaf(v.y, fmaxf(fmaf(P3, v.x, Q3), 0.0f), G3);
                }
            }
        } else {
            for (int k = 0; k < m; k++) {
                int s = __shfl_sync(FULL, idx, gbase + k);
                if (s >= 0) {
                    float2 v = g_sv[s];
                    G0 = fmaf(v.y, fmaxf(fmaf(P0, v.x, Q0), 0.0f), G0);
                    G1 = fmaf(v.y, fmaxf(fmaf(P1, v.x, Q1), 0.0f), G1);
                    G2 = fmaf(v.y, fmaxf(fmaf(P2, v.x, Q2), 0.0f), G2);
                    G3 = fmaf(v.y, fmaxf(fmaf(P3, v.x, Q3), 0.0f), G3);
                }
            }
        }
    }

    // Ghat = dinv_i * G; matvec W2 + bias b2
    float Gh[4] = {dinv * G0, dinv * G1, dinv * G2, dinv * G3};
    float4 vb2 = *(const float4*)&b2[f0];
    float t0 = vb2.x, t1 = vb2.y, t2 = vb2.z, t3 = vb2.w;
#pragma unroll
    for (int k = 0; k < 32; k++) {
        float gk = __shfl_sync(FULL, Gh[k & 3], gbase + (k >> 2));
        float4 w = *(const float4*)&sW2[k * HD + f0];
        t0 = fmaf(gk, w.x, t0);
        t1 = fmaf(gk, w.y, t1);
        t2 = fmaf(gk, w.z, t2);
        t3 = fmaf(gk, w.w, t3);
    }

    // BN2 + relu; z = dinv * y2 stored fp16
    float4 vg2 = *(const float4*)&g2[f0];
    float4 vB2 = *(const float4*)&B2[f0];
    float4 vm2 = *(const float4*)&m2[f0];
    float4 vv2 = *(const float4*)&v2[f0];
    float C0 = vg2.x * rsqrtf(vv2.x + BN_EPS);
    float C1 = vg2.y * rsqrtf(vv2.y + BN_EPS);
    float C2 = vg2.z * rsqrtf(vv2.z + BN_EPS);
    float C3 = vg2.w * rsqrtf(vv2.w + BN_EPS);
    float z0 = dinv * fmaxf(fmaf(t0, C0, fmaf(-vm2.x, C0, vB2.x)), 0.0f);
    float z1 = dinv * fmaxf(fmaf(t1, C1, fmaf(-vm2.y, C1, vB2.y)), 0.0f);
    float z2 = dinv * fmaxf(fmaf(t2, C2, fmaf(-vm2.z, C2, vB2.z)), 0.0f);
    float z3 = dinv * fmaxf(fmaf(t3, C3, fmaf(-vm2.w, C3, vB2.w)), 0.0f);

    g_z[node * 8 + sub] = make_uint2(pack_h2(z0, z1), pack_h2(z2, z3));
}

// ---------------- final: fp16-row gather, pool pre-W3 vectors ----------------
__global__ __launch_bounds__(256)
void k_final(const int* __restrict__ batch) {
    __shared__ float sacc[32][HD];
    __shared__ int   sg[32];
    int tid = threadIdx.x;
    int warp = tid >> 5, lane = tid & 31;
    int q = lane >> 3, sub = lane & 7;
    int node = blockIdx.x * 32 + warp * 4 + q;
    int f0 = sub * 4;
    int nl = warp * 4 + q;
    int gbase = lane & 24;

    // self row
    uint2 selfv = g_z[node * 8 + sub];
    float2 flo = __half22float2(*(__half2*)&selfv.x);
    float2 fhi = __half22float2(*(__half2*)&selfv.y);

    int dg = g_deg[node]; if (dg > CAP) dg = CAP;
    int mm1 = max(dg, __shfl_xor_sync(FULL, dg, 8));
    int dgmax = max(mm1, __shfl_xor_sync(FULL, mm1, 16));
    int beg = node * CAP;
    for (int j = 0; j < dgmax; j += 8) {
        int idx = (j + sub < dg) ? g_srcs[beg + j + sub] : -1;
        int m = dgmax - j; if (m > 8) m = 8;
        if (m == 8) {
#pragma unroll
            for (int k = 0; k < 8; k++) {
                int s = __shfl_sync(FULL, idx, gbase + k);
                if (s >= 0) {
                    uint2 v = g_z[s * 8 + sub];
                    float2 lo = __half22float2(*(__half2*)&v.x);
                    float2 hi = __half22float2(*(__half2*)&v.y);
                    flo.x += lo.x; flo.y += lo.y; fhi.x += hi.x; fhi.y += hi.y;
                }
            }
        } else {
            for (int k = 0; k < m; k++) {
                int s = __shfl_sync(FULL, idx, gbase + k);
                if (s >= 0) {
                    uint2 v = g_z[s * 8 + sub];
                    float2 lo = __half22float2(*(__half2*)&v.x);
                    float2 hi = __half22float2(*(__half2*)&v.y);
                    flo.x += lo.x; flo.y += lo.y; fhi.x += hi.x; fhi.y += hi.y;
                }
            }
        }
    }

    float dinv = g_dinv[node];
    float4 o = make_float4(dinv * flo.x, dinv * flo.y, dinv * fhi.x, dinv * fhi.y);
    if (sub == 0) sg[nl] = batch[node];
    *(float4*)&sacc[nl][f0] = o;
    __syncthreads();

    if (warp == 0) {
        int g0 = sg[0];
        bool uni = true;
#pragma unroll
        for (int w = 1; w < 32; w++) uni &= (sg[w] == g0);
        if (uni) {
            float s = 0.0f;
#pragma unroll
            for (int w = 0; w < 32; w++) s += sacc[w][lane];
            atomicAdd(&g_pool[g0 * HD + lane], s);
        } else {
#pragma unroll
            for (int w = 0; w < 32; w++)
                atomicAdd(&g_pool[sg[w] * HD + lane], sacc[w][lane]);
        }
    }
}

// ---------------- epilogue: out = W3^T (pool/n) + b3 ----------------
__global__ void k_div(const float* __restrict__ W3, const float* __restrict__ b3,
                      float* __restrict__ out) {
    int i = blockIdx.x * blockDim.x + threadIdx.x;
    if (i >= NG * HD) return;
    int g = i >> 5, f = i & 31;
    float inv = 1.0f / fmaxf(g_cnt[g], 1.0f);
    float s = b3[f];
#pragma unroll
    for (int k = 0; k < 32; k++)
        s = fmaf(W3[k * HD + f], g_pool[g * HD + k] * inv, s);
    out[i] = s;
}

extern "C" void kernel_launch(void* const* d_in, const int* in_sizes, int n_in,
                              void* d_out, int out_size) {
    const float* x     = (const float*)d_in[0];
    const int*   ei    = (const int*)d_in[1];
    const int*   batch = (const int*)d_in[2];
    const float* W1 = (const float*)d_in[3];
    const float* b1 = (const float*)d_in[4];
    const float* g1 = (const float*)d_in[5];
    const float* B1 = (const float*)d_in[6];
    const float* m1 = (const float*)d_in[7];
    const float* v1 = (const float*)d_in[8];
    const float* W2 = (const float*)d_in[9];
    const float* b2 = (const float*)d_in[10];
    const float* g2 = (const float*)d_in[11];
    const float* B2 = (const float*)d_in[12];
    const float* m2 = (const float*)d_in[13];
    const float* v2 = (const float*)d_in[14];
    const float* W3 = (const float*)d_in[15];
    const float* b3 = (const float*)d_in[16];
    float* out = (float*)d_out;

    const int T = 256;
    k_init<<<(NN + T - 1) / T, T>>>();
    k_fill<<<(NE / 8 + T - 1) / T, T>>>(ei);
    k_prep<<<(NN + T - 1) / T, T>>>(x, batch);

    k_layer1<<<NN / 32, T>>>();
    k_mid<<<NN / 32, T>>>(W1, b1, g1, B1, m1, v1, W2, b2, g2, B2, m2, v2);
    k_final<<<NN / 32, T>>>(batch);
    k_div<<<(NG * HD + T - 1) / T, T>>>(W3, b3, out);
}